// round 3
// baseline (speedup 1.0000x reference)
#include <cuda_runtime.h>

// out[r, c] = x[r, c] * weight[c]   for x: [32768, 1024] fp32, weight: [1024] fp32
//
// Pure HBM-streaming kernel: 128 MiB in + 128 MiB out, zero reuse of x/out.
// At the DRAM roofline (ncu-window ~7.5 TB/s effective). This round trims
// front-end cost only:
// - 32-bit indexing (max float4 index 8Mi < 2^31): shorter IMAD chains,
//   fewer regs -> better occupancy, faster CTA ramp-in.
// - 512-thread CTAs: half the blocks (2048), fewer wave transitions.
// - weight hoist: with stride-512 unroll over 256-float4 rows,
//   column-vec index == tid & 255 for every iteration -> one w load.
// - __ldcs/__stcs streaming hints (single-touch data, 256 MB >> 126 MB L2).

static constexpr int ROWS = 32768;
static constexpr int COLS = 1024;
static constexpr unsigned N_VEC4 = (unsigned)ROWS * (COLS / 4);   // 8,388,608
static constexpr int THREADS = 512;
static constexpr int VEC_PER_THREAD = 8;
static constexpr int BLOCKS = (int)(N_VEC4 / (THREADS * VEC_PER_THREAD)); // 2048
static constexpr int COLS_VEC4 = COLS / 4;                        // 256
static_assert(THREADS % COLS_VEC4 == 0, "weight-hoist needs THREADS multiple of COLS/4");

__global__ __launch_bounds__(THREADS)
void diag_weight_kernel(const float4* __restrict__ x,
                        const float4* __restrict__ w,
                        float4* __restrict__ out) {
    const unsigned tid = threadIdx.x;
    // 32-bit everywhere: base < 8Mi, byte offset < 2^27.
    const unsigned base = blockIdx.x * (unsigned)(THREADS * VEC_PER_THREAD) + tid;

    // One weight vector per thread: (base + i*512) mod 256 == tid & 255.
    const float4 vw = w[tid & (COLS_VEC4 - 1)];

    float4 vx[VEC_PER_THREAD];

    // Front-batch all 8 streaming loads (MLP=8 per thread).
#pragma unroll
    for (int i = 0; i < VEC_PER_THREAD; i++) {
        vx[i] = __ldcs(&x[base + (unsigned)i * THREADS]);
    }

#pragma unroll
    for (int i = 0; i < VEC_PER_THREAD; i++) {
        float4 r;
        r.x = vx[i].x * vw.x;
        r.y = vx[i].y * vw.y;
        r.z = vx[i].z * vw.z;
        r.w = vx[i].w * vw.w;
        __stcs(&out[base + (unsigned)i * THREADS], r);
    }
}

extern "C" void kernel_launch(void* const* d_in, const int* in_sizes, int n_in,
                              void* d_out, int out_size) {
    const float4* x = (const float4*)d_in[0];   // [32768, 1024] fp32
    const float4* w = (const float4*)d_in[1];   // [1024] fp32
    float4* out = (float4*)d_out;

    diag_weight_kernel<<<BLOCKS, THREADS>>>(x, w, out);
}

// round 4
// speedup vs baseline: 1.0007x; 1.0007x over previous
#include <cuda_runtime.h>

// out[r, c] = x[r, c] * weight[c]   for x: [32768, 1024] fp32, weight: [1024] fp32
//
// HBM-streaming at the roofline (~7.5 TB/s in steady state). R4: revert to the
// best config (256-thread CTAs, 8x float4 front-batched, streaming hints) and
// cut wave-transition overhead by having each CTA loop over 2 chunks instead
// of launching 2x the CTAs. The loop back-edge costs ~3 ALU ops; a fresh CTA
// costs a wave-transition + prologue.

static constexpr int ROWS = 32768;
static constexpr int COLS = 1024;
static constexpr unsigned N_VEC4 = (unsigned)ROWS * (COLS / 4);   // 8,388,608
static constexpr int THREADS = 256;
static constexpr int VEC_PER_THREAD = 8;                           // per chunk
static constexpr int CHUNKS_PER_CTA = 2;
static constexpr unsigned CHUNK_VEC4 = THREADS * VEC_PER_THREAD;   // 2048
static constexpr int BLOCKS =
    (int)(N_VEC4 / (CHUNK_VEC4 * CHUNKS_PER_CTA));                 // 2048
static constexpr int COLS_VEC4 = COLS / 4;                         // 256
static_assert(THREADS == COLS_VEC4, "weight-hoist relies on THREADS == COLS/4");
static_assert((unsigned)BLOCKS * CHUNK_VEC4 * CHUNKS_PER_CTA == N_VEC4, "exact cover");

__global__ __launch_bounds__(THREADS)
void diag_weight_kernel(const float4* __restrict__ x,
                        const float4* __restrict__ w,
                        float4* __restrict__ out) {
    const unsigned tid = threadIdx.x;

    // One weight vector per thread: every index this thread touches is
    // congruent to tid (mod 256). Cached load (reused by all chunks).
    const float4 vw = w[tid];

    // CTA's first chunk; chunks are contiguous per CTA.
    unsigned base = blockIdx.x * (CHUNK_VEC4 * CHUNKS_PER_CTA) + tid;

#pragma unroll
    for (int c = 0; c < CHUNKS_PER_CTA; c++) {
        float4 vx[VEC_PER_THREAD];

        // Front-batch all 8 streaming loads (MLP burst = 8 per thread).
#pragma unroll
        for (int i = 0; i < VEC_PER_THREAD; i++) {
            vx[i] = __ldcs(&x[base + (unsigned)i * THREADS]);
        }

#pragma unroll
        for (int i = 0; i < VEC_PER_THREAD; i++) {
            float4 r;
            r.x = vx[i].x * vw.x;
            r.y = vx[i].y * vw.y;
            r.z = vx[i].z * vw.z;
            r.w = vx[i].w * vw.w;
            __stcs(&out[base + (unsigned)i * THREADS], r);
        }

        base += CHUNK_VEC4;
    }
}

extern "C" void kernel_launch(void* const* d_in, const int* in_sizes, int n_in,
                              void* d_out, int out_size) {
    const float4* x = (const float4*)d_in[0];   // [32768, 1024] fp32
    const float4* w = (const float4*)d_in[1];   // [1024] fp32
    float4* out = (float4*)d_out;

    diag_weight_kernel<<<BLOCKS, THREADS>>>(x, w, out);
}

// round 5
// speedup vs baseline: 1.0272x; 1.0265x over previous
#include <cuda_runtime.h>

// out[r, c] = x[r, c] * weight[c]   for x: [32768, 1024] fp32, weight: [1024] fp32
//
// HBM-streaming at the roofline. R5: finest one-shot CTA granularity.
// Lesson from R2 vs R3/R4: fine-grained one-shot CTAs beat looping/fat CTAs
// because 2^12 chunks over 148 SMs is ragged and the HW scheduler balances it
// best with small uniform CTAs. 128-thread CTAs, 8x float4 each, 8192 blocks.
// With 128 threads the column vec-index alternates tid / tid+128 across the
// stride-128 unroll -> hoist TWO weight vectors (4 KiB table, L1-resident).

static constexpr int ROWS = 32768;
static constexpr int COLS = 1024;
static constexpr unsigned N_VEC4 = (unsigned)ROWS * (COLS / 4);   // 8,388,608
static constexpr int THREADS = 128;
static constexpr int VEC_PER_THREAD = 8;
static constexpr unsigned CHUNK_VEC4 = THREADS * VEC_PER_THREAD;  // 1024
static constexpr int BLOCKS = (int)(N_VEC4 / CHUNK_VEC4);         // 8192
static constexpr int COLS_VEC4 = COLS / 4;                        // 256
static_assert((unsigned)BLOCKS * CHUNK_VEC4 == N_VEC4, "exact cover");

__global__ __launch_bounds__(THREADS)
void diag_weight_kernel(const float4* __restrict__ x,
                        const float4* __restrict__ w,
                        float4* __restrict__ out) {
    const unsigned tid = threadIdx.x;
    const unsigned base = blockIdx.x * CHUNK_VEC4 + tid;

    // Column vec-index of iteration i is (base + i*128) mod 256, which
    // alternates between tid and tid+128 (CHUNK starts at a multiple of 1024,
    // so base mod 256 == tid). Two cached weight loads cover all 8 iters.
    const float4 vw0 = w[tid];          // even iterations
    const float4 vw1 = w[tid + 128];    // odd iterations

    float4 vx[VEC_PER_THREAD];

    // Front-batch all 8 streaming loads (MLP burst = 8 per thread).
#pragma unroll
    for (int i = 0; i < VEC_PER_THREAD; i++) {
        vx[i] = __ldcs(&x[base + (unsigned)i * THREADS]);
    }

#pragma unroll
    for (int i = 0; i < VEC_PER_THREAD; i++) {
        const float4 vw = (i & 1) ? vw1 : vw0;
        float4 r;
        r.x = vx[i].x * vw.x;
        r.y = vx[i].y * vw.y;
        r.z = vx[i].z * vw.z;
        r.w = vx[i].w * vw.w;
        __stcs(&out[base + (unsigned)i * THREADS], r);
    }
}

extern "C" void kernel_launch(void* const* d_in, const int* in_sizes, int n_in,
                              void* d_out, int out_size) {
    const float4* x = (const float4*)d_in[0];   // [32768, 1024] fp32
    const float4* w = (const float4*)d_in[1];   // [1024] fp32
    float4* out = (float4*)d_out;

    diag_weight_kernel<<<BLOCKS, THREADS>>>(x, w, out);
}